// round 3
// baseline (speedup 1.0000x reference)
#include <cuda_runtime.h>
#include <math.h>
#include <stdint.h>
#include <stddef.h>

// ---------------- problem constants ----------------
#define BSZ 2
#define HH 96
#define WW 96
#define LS 9216          // H*W
#define CC 96            // d_model
#define DD 192           // d_inner
#define NS 16            // d_state
#define KD 4             // K directions
#define RR 6             // dt_rank
#define XD 152           // K*(RR+2*NS)/K per k = 38; stacked = 152
#define NCH 96           // number of chunks
#define CHL 96           // chunk length (NCH*CHL == LS)
#define MPIX (BSZ*LS)    // 18432

// ---------------- scratch (static device memory; no allocs) ----------------
__device__ float g_xn   [BSZ*LS*CC];          // LN'd input, (B,L,C)
__device__ float g_xz   [BSZ*LS*2*DD];        // in_proj out, (B,L,384): [0:192)=xi, [192:384)=z
__device__ float g_u    [BSZ*LS*DD];          // conv+silu out, (B,L,D)
__device__ float g_xdbl [BSZ*LS*XD];          // x_proj out per pixel, (B,L,152)
__device__ float g_P    [BSZ*KD*NCH*DD*NS];   // chunk decay products -> then h_in
__device__ float g_hend [BSZ*KD*NCH*DD*NS];   // chunk local end states
__device__ float g_oy   [BSZ*KD*LS*DD];       // scan outputs, (B,K,L(t),D)
__device__ float g_ypost[BSZ*LS*DD];          // combined + LN + silu(z) gate
__device__ float g_t96  [BSZ*LS*CC];          // out_proj out / fc2 out
__device__ float g_x2   [BSZ*LS*CC];          // residual-1 result (== yb)
__device__ float g_h1n  [BSZ*LS*CC];          // LN_ffn(x2)
__device__ float g_t192 [BSZ*LS*DD];          // fc1 out

// ---------------- helpers ----------------
__device__ __forceinline__ float softplusf(float x) {
    return fmaxf(x, 0.f) + log1pf(__expf(-fabsf(x)));
}
__device__ __forceinline__ float siluf(float x) {
    return x / (1.f + __expf(-x));
}
// spatial position (row-major p = h*W + w) visited by direction k at scan time t
__device__ __forceinline__ int pos_of(int k, int t) {
    int tt = (k >= 2) ? (LS - 1 - t) : t;
    if (k & 1) { int w = tt / HH; int h = tt - w * HH; return h * WW + w; }
    return tt;
}

// ---------------- LN over channel dim of NCHW input -> (B,L,C) ----------------
__global__ void ln_in_kernel(const float* __restrict__ x,
                             const float* __restrict__ g, const float* __restrict__ bb) {
    int warp = (blockIdx.x * blockDim.x + threadIdx.x) >> 5;
    int lane = threadIdx.x & 31;
    if (warp >= MPIX) return;
    int b = warp / LS, p = warp - b * LS;
    float v[3], s = 0.f, ss = 0.f;
#pragma unroll
    for (int j = 0; j < 3; j++) {
        int c = lane + j * 32;
        v[j] = x[((size_t)(b * CC + c)) * LS + p];
        s += v[j]; ss += v[j] * v[j];
    }
#pragma unroll
    for (int o = 16; o > 0; o >>= 1) { s += __shfl_xor_sync(~0u, s, o); ss += __shfl_xor_sync(~0u, ss, o); }
    float m = s * (1.f / CC);
    float var = ss * (1.f / CC) - m * m;
    float inv = rsqrtf(var + 1e-6f);
#pragma unroll
    for (int j = 0; j < 3; j++) {
        int c = lane + j * 32;
        g_xn[(size_t)warp * CC + c] = (v[j] - m) * inv * g[c] + bb[c];
    }
}

// ---------------- generic fp32 tiled GEMM: C[m,n] = act(A[m,:K].W[n,:K] + bias[n]) ----------------
template <int ACT>
__global__ void __launch_bounds__(256) gemm_k(const float* __restrict__ A, const float* __restrict__ W,
                                              const float* __restrict__ bias, float* __restrict__ C,
                                              int M, int N, int K) {
    __shared__ float As[16][64];
    __shared__ float Ws[16][64];
    int tid = threadIdx.x;
    int tx = tid & 15, ty = tid >> 4;
    int bn = blockIdx.x * 64, bm = blockIdx.y * 64;
    float acc[4][4] = {};
    for (int k0 = 0; k0 < K; k0 += 16) {
#pragma unroll
        for (int i = 0; i < 4; i++) {
            int idx = tid + i * 256;
            int m = idx >> 4, kk = idx & 15;
            As[kk][m] = A[(size_t)(bm + m) * K + k0 + kk];
        }
#pragma unroll
        for (int i = 0; i < 4; i++) {
            int idx = tid + i * 256;
            int n = idx >> 4, kk = idx & 15;
            Ws[kk][n] = (bn + n < N) ? W[(size_t)(bn + n) * K + k0 + kk] : 0.f;
        }
        __syncthreads();
#pragma unroll
        for (int kk = 0; kk < 16; kk++) {
            float a[4], w[4];
#pragma unroll
            for (int i = 0; i < 4; i++) a[i] = As[kk][ty * 4 + i];
#pragma unroll
            for (int j = 0; j < 4; j++) w[j] = Ws[kk][tx * 4 + j];
#pragma unroll
            for (int i = 0; i < 4; i++)
#pragma unroll
                for (int j = 0; j < 4; j++) acc[i][j] += a[i] * w[j];
        }
        __syncthreads();
    }
#pragma unroll
    for (int i = 0; i < 4; i++) {
        int m = bm + ty * 4 + i;
#pragma unroll
        for (int j = 0; j < 4; j++) {
            int n = bn + tx * 4 + j;
            if (n < N) {
                float v = acc[i][j] + (bias ? bias[n] : 0.f);
                if (ACT == 1) v = (v >= 0.f) ? v : 0.01f * v;
                C[(size_t)m * N + n] = v;
            }
        }
    }
}

// ---------------- depthwise 3x3 conv + bias + SiLU ----------------
__global__ void __launch_bounds__(DD) conv_silu_kernel(const float* __restrict__ cw,
                                                       const float* __restrict__ cb) {
    int blk = blockIdx.x;           // b*LS + p
    int b = blk / LS, p = blk - b * LS;
    int d = threadIdx.x;
    int h = p / WW, w = p - h * WW;
    float acc = cb[d];
#pragma unroll
    for (int ky = 0; ky < 3; ky++) {
        int hh = h + ky - 1;
        if (hh < 0 || hh >= HH) continue;
#pragma unroll
        for (int kx = 0; kx < 3; kx++) {
            int ww2 = w + kx - 1;
            if (ww2 < 0 || ww2 >= WW) continue;
            acc += g_xz[((size_t)(b * LS + hh * WW + ww2)) * (2 * DD) + d] * cw[d * 9 + ky * 3 + kx];
        }
    }
    g_u[((size_t)(b * LS + p)) * DD + d] = siluf(acc);
}

// ---------------- scan phase 1: per-chunk decay products + local end state ----------------
__global__ void __launch_bounds__(DD) scan_p1(const float* __restrict__ dtw,
                                              const float* __restrict__ dtb,
                                              const float* __restrict__ Alogs) {
    int blk = blockIdx.x;
    int c = blk % NCH;
    int k = (blk / NCH) % KD;
    int b = blk / (NCH * KD);
    int d = threadIdx.x;

    float wdt[RR];
#pragma unroll
    for (int r = 0; r < RR; r++) wdt[r] = dtw[(k * DD + d) * RR + r];
    float bdt = dtb[k * DD + d];
    float A[NS];
#pragma unroll
    for (int n = 0; n < NS; n++) A[n] = -__expf(Alogs[(k * DD + d) * NS + n]);

    __shared__ float sx[CHL][40];
    for (int i = d; i < CHL * 38; i += DD) {
        int s = i / 38, cc = i - s * 38;
        int p = pos_of(k, c * CHL + s);
        sx[s][cc] = g_xdbl[((size_t)(b * LS + p)) * XD + k * 38 + cc];
    }
    __syncthreads();

    float h[NS], P[NS];
#pragma unroll
    for (int n = 0; n < NS; n++) { h[n] = 0.f; P[n] = 1.f; }

    const float* up = g_u + (size_t)b * LS * DD + d;
    for (int s = 0; s < CHL; s++) {
        int t = c * CHL + s;
        int p = pos_of(k, t);
        float uu = up[(size_t)p * DD];
        float sv = bdt;
#pragma unroll
        for (int r = 0; r < RR; r++) sv += sx[s][r] * wdt[r];
        float delta = softplusf(sv);
        float du = delta * uu;
#pragma unroll
        for (int n = 0; n < NS; n++) {
            float dA = __expf(delta * A[n]);
            P[n] *= dA;
            h[n] = h[n] * dA + du * sx[s][6 + n];
        }
    }
    size_t base = ((((size_t)(b * KD + k)) * NCH + c) * DD + d) * NS;
#pragma unroll
    for (int n = 0; n < NS; n++) { g_P[base + n] = P[n]; g_hend[base + n] = h[n]; }
}

// ---------------- scan phase 2: stitch chunk boundary states (overwrites g_P with h_in) ----------------
__global__ void scan_p2() {
    int gid = blockIdx.x * blockDim.x + threadIdx.x;   // B*K*D*N = 24576
    int dn = gid % (DD * NS);
    int k = (gid / (DD * NS)) % KD;
    int b = gid / (DD * NS * KD);
    float h = 0.f;
    size_t stride = (size_t)DD * NS;
    size_t base = ((size_t)(b * KD + k)) * NCH * stride + dn;
    for (int c = 0; c < NCH; c++) {
        size_t idx = base + (size_t)c * stride;
        float Pv = g_P[idx];
        float he = g_hend[idx];
        g_P[idx] = h;               // h_in for chunk c
        h = Pv * h + he;
    }
}

// ---------------- scan phase 3: full scan per chunk with correct h_in, emit y ----------------
__global__ void __launch_bounds__(DD) scan_p3(const float* __restrict__ dtw,
                                              const float* __restrict__ dtb,
                                              const float* __restrict__ Alogs,
                                              const float* __restrict__ Ds) {
    int blk = blockIdx.x;
    int c = blk % NCH;
    int k = (blk / NCH) % KD;
    int b = blk / (NCH * KD);
    int d = threadIdx.x;

    float wdt[RR];
#pragma unroll
    for (int r = 0; r < RR; r++) wdt[r] = dtw[(k * DD + d) * RR + r];
    float bdt = dtb[k * DD + d];
    float Dsv = Ds[k * DD + d];
    float A[NS];
#pragma unroll
    for (int n = 0; n < NS; n++) A[n] = -__expf(Alogs[(k * DD + d) * NS + n]);

    __shared__ float sx[CHL][40];
    for (int i = d; i < CHL * 38; i += DD) {
        int s = i / 38, cc = i - s * 38;
        int p = pos_of(k, c * CHL + s);
        sx[s][cc] = g_xdbl[((size_t)(b * LS + p)) * XD + k * 38 + cc];
    }
    __syncthreads();

    float h[NS];
    size_t base = ((((size_t)(b * KD + k)) * NCH + c) * DD + d) * NS;
#pragma unroll
    for (int n = 0; n < NS; n++) h[n] = g_P[base + n];

    const float* up = g_u + (size_t)b * LS * DD + d;
    float* oyp = g_oy + ((size_t)(b * KD + k)) * LS * DD + d;
    for (int s = 0; s < CHL; s++) {
        int t = c * CHL + s;
        int p = pos_of(k, t);
        float uu = up[(size_t)p * DD];
        float sv = bdt;
#pragma unroll
        for (int r = 0; r < RR; r++) sv += sx[s][r] * wdt[r];
        float delta = softplusf(sv);
        float du = delta * uu;
        float y = 0.f;
#pragma unroll
        for (int n = 0; n < NS; n++) {
            float dA = __expf(delta * A[n]);
            h[n] = h[n] * dA + du * sx[s][6 + n];
            y += h[n] * sx[s][22 + n];
        }
        oyp[(size_t)t * DD] = y + uu * Dsv;
    }
}

// ---------------- combine 4 directions + LN(out_norm) + gate by silu(z) ----------------
__global__ void combine_ln_silu(const float* __restrict__ gno, const float* __restrict__ bno) {
    int warp = (blockIdx.x * blockDim.x + threadIdx.x) >> 5;
    int lane = threadIdx.x & 31;
    if (warp >= MPIX) return;
    int b = warp / LS, p = warp - b * LS;
    int hh = p / WW, ww = p - hh * WW;
    int tcol = ww * HH + hh;

    size_t base0 = (((size_t)(b * KD + 0)) * LS + p) * DD;
    size_t base1 = (((size_t)(b * KD + 1)) * LS + tcol) * DD;
    size_t base2 = (((size_t)(b * KD + 2)) * LS + (LS - 1 - p)) * DD;
    size_t base3 = (((size_t)(b * KD + 3)) * LS + (LS - 1 - tcol)) * DD;

    float v[6], s = 0.f, ss = 0.f;
#pragma unroll
    for (int j = 0; j < 6; j++) {
        int dd = lane + j * 32;
        float t = g_oy[base0 + dd] + g_oy[base1 + dd] + g_oy[base2 + dd] + g_oy[base3 + dd];
        v[j] = t; s += t; ss += t * t;
    }
#pragma unroll
    for (int o = 16; o > 0; o >>= 1) { s += __shfl_xor_sync(~0u, s, o); ss += __shfl_xor_sync(~0u, ss, o); }
    float m = s * (1.f / DD);
    float var = ss * (1.f / DD) - m * m;
    float inv = rsqrtf(var + 1e-5f);
#pragma unroll
    for (int j = 0; j < 6; j++) {
        int dd = lane + j * 32;
        float z = g_xz[((size_t)warp) * (2 * DD) + DD + dd];
        float yn = (v[j] - m) * inv * gno[dd] + bno[dd];
        g_ypost[(size_t)warp * DD + dd] = yn * siluf(z);
    }
}

// ---------------- residual 1 (+ scale1 * x) and LN_ffn ----------------
__global__ void resid1_lnffn(const float* __restrict__ x, const float* __restrict__ scale1,
                             const float* __restrict__ gf, const float* __restrict__ bf) {
    int warp = (blockIdx.x * blockDim.x + threadIdx.x) >> 5;
    int lane = threadIdx.x & 31;
    if (warp >= MPIX) return;
    int b = warp / LS, p = warp - b * LS;
    float v[3], s = 0.f, ss = 0.f;
#pragma unroll
    for (int j = 0; j < 3; j++) {
        int c = lane + j * 32;
        float t = g_t96[(size_t)warp * CC + c] + x[((size_t)(b * CC + c)) * LS + p] * scale1[c];
        v[j] = t; s += t; ss += t * t;
        g_x2[(size_t)warp * CC + c] = t;
    }
#pragma unroll
    for (int o = 16; o > 0; o >>= 1) { s += __shfl_xor_sync(~0u, s, o); ss += __shfl_xor_sync(~0u, ss, o); }
    float m = s * (1.f / CC);
    float var = ss * (1.f / CC) - m * m;
    float inv = rsqrtf(var + 1e-5f);
#pragma unroll
    for (int j = 0; j < 3; j++) {
        int c = lane + j * 32;
        g_h1n[(size_t)warp * CC + c] = (v[j] - m) * inv * gf[c] + bf[c];
    }
}

// ---------------- final: residual 2 + transpose to (B,C,H,W) ----------------
__global__ void final_kernel(const float* __restrict__ scale2, float* __restrict__ out) {
    int gid = blockIdx.x * blockDim.x + threadIdx.x;   // (b*CC + c)*LS + p
    if (gid >= BSZ * CC * LS) return;
    int p = gid % LS;
    int c = (gid / LS) % CC;
    int b = gid / (LS * CC);
    size_t src = ((size_t)(b * LS + p)) * CC + c;
    out[gid] = g_t96[src] + g_x2[src] * scale2[c];
}

// ---------------- launch ----------------
extern "C" void kernel_launch(void* const* d_in, const int* in_sizes, int n_in,
                              void* d_out, int out_size) {
    const float* x          = (const float*)d_in[0];
    const float* ln_in_g    = (const float*)d_in[1];
    const float* ln_in_b    = (const float*)d_in[2];
    const float* in_proj_w  = (const float*)d_in[3];
    const float* in_proj_b  = (const float*)d_in[4];
    const float* conv_w     = (const float*)d_in[5];
    const float* conv_b     = (const float*)d_in[6];
    const float* x_proj_w   = (const float*)d_in[7];
    const float* dt_w       = (const float*)d_in[8];
    const float* dt_b       = (const float*)d_in[9];
    const float* A_logs     = (const float*)d_in[10];
    const float* Ds         = (const float*)d_in[11];
    const float* out_norm_g = (const float*)d_in[12];
    const float* out_norm_b = (const float*)d_in[13];
    const float* out_proj_w = (const float*)d_in[14];
    const float* out_proj_b = (const float*)d_in[15];
    const float* ln_ffn_g   = (const float*)d_in[16];
    const float* ln_ffn_b   = (const float*)d_in[17];
    const float* fc1_w      = (const float*)d_in[18];
    const float* fc1_b      = (const float*)d_in[19];
    const float* fc2_w      = (const float*)d_in[20];
    const float* fc2_b      = (const float*)d_in[21];
    const float* scale1     = (const float*)d_in[22];
    const float* scale2     = (const float*)d_in[23];

    float *p_xn, *p_xz, *p_u, *p_xdbl, *p_ypost, *p_t96, *p_h1n, *p_t192;
    cudaGetSymbolAddress((void**)&p_xn,    g_xn);
    cudaGetSymbolAddress((void**)&p_xz,    g_xz);
    cudaGetSymbolAddress((void**)&p_u,     g_u);
    cudaGetSymbolAddress((void**)&p_xdbl,  g_xdbl);
    cudaGetSymbolAddress((void**)&p_ypost, g_ypost);
    cudaGetSymbolAddress((void**)&p_t96,   g_t96);
    cudaGetSymbolAddress((void**)&p_h1n,   g_h1n);
    cudaGetSymbolAddress((void**)&p_t192,  g_t192);

    // 1. LN over channels -> g_xn (B,L,C)
    ln_in_kernel<<<MPIX / 8, 256>>>(x, ln_in_g, ln_in_b);
    // 2. in_proj: (M,96) x (384,96)^T -> g_xz (B,L,384)
    gemm_k<0><<<dim3(384 / 64, MPIX / 64), 256>>>(p_xn, in_proj_w, in_proj_b, p_xz, MPIX, 2 * DD, CC);
    // 3. depthwise conv 3x3 + SiLU -> g_u (B,L,192)
    conv_silu_kernel<<<MPIX, DD>>>(conv_w, conv_b);
    // 4. x_proj (all 4 k stacked): (M,192) x (152,192)^T -> g_xdbl (B,L,152)
    gemm_k<0><<<dim3(3, MPIX / 64), 256>>>(p_u, x_proj_w, nullptr, p_xdbl, MPIX, XD, DD);
    // 5-7. chunked selective scan
    scan_p1<<<BSZ * KD * NCH, DD>>>(dt_w, dt_b, A_logs);
    scan_p2<<<(BSZ * KD * DD * NS) / 256, 256>>>();
    scan_p3<<<BSZ * KD * NCH, DD>>>(dt_w, dt_b, A_logs, Ds);
    // 8. combine 4 directions + LN + silu(z) gate -> g_ypost (B,L,192)
    combine_ln_silu<<<MPIX / 8, 256>>>(out_norm_g, out_norm_b);
    // 9. out_proj: (M,192) x (96,192)^T -> g_t96
    gemm_k<0><<<dim3(2, MPIX / 64), 256>>>(p_ypost, out_proj_w, out_proj_b, p_t96, MPIX, CC, DD);
    // 10. residual1 + LN_ffn -> g_x2, g_h1n
    resid1_lnffn<<<MPIX / 8, 256>>>(x, scale1, ln_ffn_g, ln_ffn_b);
    // 11. fc1 + leaky relu: (M,96) x (192,96)^T -> g_t192
    gemm_k<1><<<dim3(3, MPIX / 64), 256>>>(p_h1n, fc1_w, fc1_b, p_t192, MPIX, DD, CC);
    // 12. fc2: (M,192) x (96,192)^T -> g_t96
    gemm_k<0><<<dim3(2, MPIX / 64), 256>>>(p_t192, fc2_w, fc2_b, p_t96, MPIX, CC, DD);
    // 13. residual2 + transpose to (B,C,H,W)
    final_kernel<<<(BSZ * CC * LS) / 256, 256>>>(scale2, (float*)d_out);
}

// round 6
// speedup vs baseline: 1.7535x; 1.7535x over previous
#include <cuda_runtime.h>
#include <math.h>
#include <stdint.h>
#include <stddef.h>

// ---------------- problem constants ----------------
#define BSZ 2
#define HH 96
#define WW 96
#define LS 9216          // H*W
#define CC 96            // d_model
#define DD 192           // d_inner
#define NS 16            // d_state
#define KD 4             // K directions
#define RR 6             // dt_rank
#define XD 152           // stacked x_proj output dim
#define NCH 96           // number of chunks
#define CHL 96           // chunk length
#define MPIX (BSZ*LS)    // 18432

typedef unsigned long long u64;

// ---------------- scratch ----------------
__device__ float g_xn   [BSZ*LS*CC];
__device__ float g_xz   [BSZ*LS*2*DD];
__device__ float g_u    [BSZ*LS*DD];
__device__ float g_xdbl [BSZ*LS*XD];
__device__ float g_P    [BSZ*KD*NCH*DD*NS];
__device__ float g_hend [BSZ*KD*NCH*DD*NS];
__device__ float g_oy   [BSZ*KD*LS*DD];
__device__ float g_ypost[BSZ*LS*DD];
__device__ float g_t96  [BSZ*LS*CC];
__device__ float g_x2   [BSZ*LS*CC];
__device__ float g_h1n  [BSZ*LS*CC];
__device__ float g_t192 [BSZ*LS*DD];

// ---------------- f32x2 packed helpers ----------------
__device__ __forceinline__ u64 pk2(float lo, float hi) {
    u64 r;
    asm("mov.b64 %0, {%1, %2};" : "=l"(r) : "r"(__float_as_uint(lo)), "r"(__float_as_uint(hi)));
    return r;
}
__device__ __forceinline__ u64 dup2(float v) {
    u64 r;
    asm("mov.b64 %0, {%1, %1};" : "=l"(r) : "r"(__float_as_uint(v)));
    return r;
}
__device__ __forceinline__ u64 fma2(u64 a, u64 b, u64 c) {
    u64 d;
    asm("fma.rn.f32x2 %0, %1, %2, %3;" : "=l"(d) : "l"(a), "l"(b), "l"(c));
    return d;
}
__device__ __forceinline__ u64 mul2(u64 a, u64 b) {
    u64 d;
    asm("mul.rn.f32x2 %0, %1, %2;" : "=l"(d) : "l"(a), "l"(b));
    return d;
}
__device__ __forceinline__ void unpk2(u64 v, float& lo, float& hi) {
    unsigned int a, b;
    asm("mov.b64 {%0, %1}, %2;" : "=r"(a), "=r"(b) : "l"(v));
    lo = __uint_as_float(a); hi = __uint_as_float(b);
}

// ---------------- math helpers ----------------
__device__ __forceinline__ float softplusf(float x) {
    return fmaxf(x, 0.f) + log1pf(__expf(-fabsf(x)));
}
__device__ __forceinline__ float siluf(float x) {
    return x / (1.f + __expf(-x));
}
__device__ __forceinline__ int pos_of(int k, int t) {
    int tt = (k >= 2) ? (LS - 1 - t) : t;
    if (k & 1) { int w = tt / HH; int h = tt - w * HH; return h * WW + w; }
    return tt;
}

// ---------------- LN over channels of NCHW -> (B,L,C) ----------------
__global__ void ln_in_kernel(const float* __restrict__ x,
                             const float* __restrict__ g, const float* __restrict__ bb) {
    int warp = (blockIdx.x * blockDim.x + threadIdx.x) >> 5;
    int lane = threadIdx.x & 31;
    if (warp >= MPIX) return;
    int b = warp / LS, p = warp - b * LS;
    float v[3], s = 0.f, ss = 0.f;
#pragma unroll
    for (int j = 0; j < 3; j++) {
        int c = lane + j * 32;
        v[j] = x[((size_t)(b * CC + c)) * LS + p];
        s += v[j]; ss += v[j] * v[j];
    }
#pragma unroll
    for (int o = 16; o > 0; o >>= 1) { s += __shfl_xor_sync(~0u, s, o); ss += __shfl_xor_sync(~0u, ss, o); }
    float m = s * (1.f / CC);
    float var = ss * (1.f / CC) - m * m;
    float inv = rsqrtf(var + 1e-6f);
#pragma unroll
    for (int j = 0; j < 3; j++) {
        int c = lane + j * 32;
        g_xn[(size_t)warp * CC + c] = (v[j] - m) * inv * g[c] + bb[c];
    }
}

// ---------------- f32x2 GEMM: 128(M)x64(N) tile, 256 thr, 8x4 micro (m-pairs) -----
// C[m,n] = act(sum_k A[m,k]*W[n,k] + bias[n]);  requires M%128==0, K%16==0, N%4==0
template <int ACT>
__global__ void __launch_bounds__(256) gemm2(const float* __restrict__ A, const float* __restrict__ W,
                                             const float* __restrict__ bias, float* __restrict__ C,
                                             int M, int N, int K) {
    __shared__ __align__(16) float As[16][130];
    __shared__ __align__(16) float Ws[16][68];
    int t = threadIdx.x;
    int bn = blockIdx.x * 64, bm = blockIdx.y * 128;
    int tx = t & 15, ty = t >> 4;
    int m0 = ty * 8, n0 = tx * 4;

    u64 acc[4][4];
#pragma unroll
    for (int i = 0; i < 4; i++)
#pragma unroll
        for (int j = 0; j < 4; j++) acc[i][j] = 0ull;

    int lrow = t >> 2;        // 0..63
    int lc4  = t & 3;         // float4 slot within 16-wide k

    for (int k0 = 0; k0 < K; k0 += 16) {
        // A: 128x16 -> transposed As[kk][m]
#pragma unroll
        for (int r = 0; r < 2; r++) {
            int row = lrow + r * 64;
            float4 v = *(const float4*)&A[(size_t)(bm + row) * K + k0 + lc4 * 4];
            As[lc4 * 4 + 0][row] = v.x; As[lc4 * 4 + 1][row] = v.y;
            As[lc4 * 4 + 2][row] = v.z; As[lc4 * 4 + 3][row] = v.w;
        }
        // W: 64x16 -> Ws[kk][n]
        {
            float4 v = make_float4(0.f, 0.f, 0.f, 0.f);
            if (bn + lrow < N) v = *(const float4*)&W[(size_t)(bn + lrow) * K + k0 + lc4 * 4];
            Ws[lc4 * 4 + 0][lrow] = v.x; Ws[lc4 * 4 + 1][lrow] = v.y;
            Ws[lc4 * 4 + 2][lrow] = v.z; Ws[lc4 * 4 + 3][lrow] = v.w;
        }
        __syncthreads();
#pragma unroll
        for (int kk = 0; kk < 16; kk++) {
            u64 a[4], wp[4];
#pragma unroll
            for (int i = 0; i < 4; i++) a[i] = *(const u64*)&As[kk][m0 + 2 * i];
#pragma unroll
            for (int j = 0; j < 4; j++) wp[j] = dup2(Ws[kk][n0 + j]);
#pragma unroll
            for (int i = 0; i < 4; i++)
#pragma unroll
                for (int j = 0; j < 4; j++) acc[i][j] = fma2(a[i], wp[j], acc[i][j]);
        }
        __syncthreads();
    }
    if (bn + n0 < N) {
        float bv[4];
#pragma unroll
        for (int j = 0; j < 4; j++) bv[j] = bias ? bias[bn + n0 + j] : 0.f;
#pragma unroll
        for (int i = 0; i < 4; i++) {
            float lo[4], hi[4];
#pragma unroll
            for (int j = 0; j < 4; j++) {
                unpk2(acc[i][j], lo[j], hi[j]);
                lo[j] += bv[j]; hi[j] += bv[j];
                if (ACT == 1) {
                    lo[j] = lo[j] >= 0.f ? lo[j] : 0.01f * lo[j];
                    hi[j] = hi[j] >= 0.f ? hi[j] : 0.01f * hi[j];
                }
            }
            int m = bm + m0 + 2 * i;
            *(float4*)&C[(size_t)m * N + bn + n0]       = make_float4(lo[0], lo[1], lo[2], lo[3]);
            *(float4*)&C[(size_t)(m + 1) * N + bn + n0] = make_float4(hi[0], hi[1], hi[2], hi[3]);
        }
    }
}

// ---------------- depthwise 3x3 conv + bias + SiLU ----------------
__global__ void __launch_bounds__(DD) conv_silu_kernel(const float* __restrict__ cw,
                                                       const float* __restrict__ cb) {
    int blk = blockIdx.x;
    int b = blk / LS, p = blk - b * LS;
    int d = threadIdx.x;
    int h = p / WW, w = p - h * WW;
    float acc = cb[d];
#pragma unroll
    for (int ky = 0; ky < 3; ky++) {
        int hh = h + ky - 1;
        if (hh < 0 || hh >= HH) continue;
#pragma unroll
        for (int kx = 0; kx < 3; kx++) {
            int ww2 = w + kx - 1;
            if (ww2 < 0 || ww2 >= WW) continue;
            acc += g_xz[((size_t)(b * LS + hh * WW + ww2)) * (2 * DD) + d] * cw[d * 9 + ky * 3 + kx];
        }
    }
    g_u[((size_t)(b * LS + p)) * DD + d] = siluf(acc);
}

// ---------------- scan phase 1: chunk decay (via sum of delta) + local end state ----
__global__ void __launch_bounds__(DD) scan_p1(const float* __restrict__ dtw,
                                              const float* __restrict__ dtb,
                                              const float* __restrict__ Alogs) {
    int blk = blockIdx.x;
    int c = blk % NCH;
    int k = (blk / NCH) % KD;
    int b = blk / (NCH * KD);
    int d = threadIdx.x;

    float wdt[RR];
#pragma unroll
    for (int r = 0; r < RR; r++) wdt[r] = dtw[(k * DD + d) * RR + r];
    float bdt = dtb[k * DD + d];
    float A[NS];
    bool powok = true;
#pragma unroll
    for (int n = 0; n < NS; n++) {
        float an = __expf(Alogs[(k * DD + d) * NS + n]);
        A[n] = -an;
        powok = powok && (fabsf(an - (float)(n + 1)) < 1e-3f * (float)(n + 1));
    }

    __shared__ __align__(16) float sx[CHL][40];
    for (int i = d; i < CHL * 38; i += DD) {
        int s = i / 38, cc = i - s * 38;
        int p = pos_of(k, c * CHL + s);
        sx[s][cc] = g_xdbl[((size_t)(b * LS + p)) * XD + k * 38 + cc];
    }
    __syncthreads();

    const float* up = g_u + (size_t)b * LS * DD + d;
    float S = 0.f;
    u64 h2[8];
#pragma unroll
    for (int j = 0; j < 8; j++) h2[j] = 0ull;

    if (powok) {
        for (int s = 0; s < CHL; s++) {
            int p = pos_of(k, c * CHL + s);
            float uu = up[(size_t)p * DD];
            float sv = bdt;
#pragma unroll
            for (int r = 0; r < RR; r++) sv += sx[s][r] * wdt[r];
            float delta = softplusf(sv);
            S += delta;
            float du = delta * uu;
            float f = __expf(-delta);
            float f2 = f * f;
            u64 q = pk2(f, f2);
            u64 ff = dup2(f2);
            u64 dup = dup2(du);
#pragma unroll
            for (int j = 0; j < 8; j++) {
                u64 Bp = *(const u64*)&sx[s][6 + 2 * j];
                h2[j] = fma2(h2[j], q, mul2(dup, Bp));
                q = mul2(q, ff);
            }
        }
    } else {
        float h[NS];
#pragma unroll
        for (int n = 0; n < NS; n++) h[n] = 0.f;
        for (int s = 0; s < CHL; s++) {
            int p = pos_of(k, c * CHL + s);
            float uu = up[(size_t)p * DD];
            float sv = bdt;
#pragma unroll
            for (int r = 0; r < RR; r++) sv += sx[s][r] * wdt[r];
            float delta = softplusf(sv);
            S += delta;
            float du = delta * uu;
#pragma unroll
            for (int n = 0; n < NS; n++) {
                float dA = __expf(delta * A[n]);
                h[n] = h[n] * dA + du * sx[s][6 + n];
            }
        }
#pragma unroll
        for (int j = 0; j < 8; j++) h2[j] = pk2(h[2 * j], h[2 * j + 1]);
    }

    size_t base = ((((size_t)(b * KD + k)) * NCH + c) * DD + d) * NS;
#pragma unroll
    for (int n = 0; n < NS; n++) g_P[base + n] = __expf(A[n] * S);
#pragma unroll
    for (int j = 0; j < 8; j++) *(u64*)&g_hend[base + 2 * j] = h2[j];
}

// ---------------- scan phase 2: stitch chunk boundaries ----------------
__global__ void scan_p2() {
    int gid = blockIdx.x * blockDim.x + threadIdx.x;   // B*K*D*N = 24576
    int dn = gid % (DD * NS);
    int k = (gid / (DD * NS)) % KD;
    int b = gid / (DD * NS * KD);
    float h = 0.f;
    size_t stride = (size_t)DD * NS;
    size_t base = ((size_t)(b * KD + k)) * NCH * stride + dn;
    for (int c = 0; c < NCH; c++) {
        size_t idx = base + (size_t)c * stride;
        float Pv = g_P[idx];
        float he = g_hend[idx];
        g_P[idx] = h;
        h = Pv * h + he;
    }
}

// ---------------- scan phase 3: full scan, emit y ----------------
__global__ void __launch_bounds__(DD) scan_p3(const float* __restrict__ dtw,
                                              const float* __restrict__ dtb,
                                              const float* __restrict__ Alogs,
                                              const float* __restrict__ Ds) {
    int blk = blockIdx.x;
    int c = blk % NCH;
    int k = (blk / NCH) % KD;
    int b = blk / (NCH * KD);
    int d = threadIdx.x;

    float wdt[RR];
#pragma unroll
    for (int r = 0; r < RR; r++) wdt[r] = dtw[(k * DD + d) * RR + r];
    float bdt = dtb[k * DD + d];
    float Dsv = Ds[k * DD + d];
    float A[NS];
    bool powok = true;
#pragma unroll
    for (int n = 0; n < NS; n++) {
        float an = __expf(Alogs[(k * DD + d) * NS + n]);
        A[n] = -an;
        powok = powok && (fabsf(an - (float)(n + 1)) < 1e-3f * (float)(n + 1));
    }

    __shared__ __align__(16) float sx[CHL][40];
    for (int i = d; i < CHL * 38; i += DD) {
        int s = i / 38, cc = i - s * 38;
        int p = pos_of(k, c * CHL + s);
        sx[s][cc] = g_xdbl[((size_t)(b * LS + p)) * XD + k * 38 + cc];
    }
    __syncthreads();

    size_t base = ((((size_t)(b * KD + k)) * NCH + c) * DD + d) * NS;
    const float* up = g_u + (size_t)b * LS * DD + d;
    float* oyp = g_oy + ((size_t)(b * KD + k)) * LS * DD + d;

    if (powok) {
        u64 h2[8];
#pragma unroll
        for (int j = 0; j < 8; j++) h2[j] = *(const u64*)&g_P[base + 2 * j];
        for (int s = 0; s < CHL; s++) {
            int t = c * CHL + s;
            int p = pos_of(k, t);
            float uu = up[(size_t)p * DD];
            float sv = bdt;
#pragma unroll
            for (int r = 0; r < RR; r++) sv += sx[s][r] * wdt[r];
            float delta = softplusf(sv);
            float du = delta * uu;
            float f = __expf(-delta);
            float f2 = f * f;
            u64 q = pk2(f, f2);
            u64 ff = dup2(f2);
            u64 dup = dup2(du);
            u64 y2 = 0ull;
#pragma unroll
            for (int j = 0; j < 8; j++) {
                u64 Bp = *(const u64*)&sx[s][6 + 2 * j];
                u64 Cp = *(const u64*)&sx[s][22 + 2 * j];
                h2[j] = fma2(h2[j], q, mul2(dup, Bp));
                y2 = fma2(h2[j], Cp, y2);
                q = mul2(q, ff);
            }
            float ylo, yhi;
            unpk2(y2, ylo, yhi);
            oyp[(size_t)t * DD] = ylo + yhi + uu * Dsv;
        }
    } else {
        float h[NS];
#pragma unroll
        for (int n = 0; n < NS; n++) h[n] = g_P[base + n];
        for (int s = 0; s < CHL; s++) {
            int t = c * CHL + s;
            int p = pos_of(k, t);
            float uu = up[(size_t)p * DD];
            float sv = bdt;
#pragma unroll
            for (int r = 0; r < RR; r++) sv += sx[s][r] * wdt[r];
            float delta = softplusf(sv);
            float du = delta * uu;
            float y = 0.f;
#pragma unroll
            for (int n = 0; n < NS; n++) {
                float dA = __expf(delta * A[n]);
                h[n] = h[n] * dA + du * sx[s][6 + n];
                y += h[n] * sx[s][22 + n];
            }
            oyp[(size_t)t * DD] = y + uu * Dsv;
        }
    }
}

// ---------------- combine 4 directions + LN(out_norm) + silu(z) gate -------------
__global__ void combine_ln_silu(const float* __restrict__ gno, const float* __restrict__ bno) {
    int warp = (blockIdx.x * blockDim.x + threadIdx.x) >> 5;
    int lane = threadIdx.x & 31;
    if (warp >= MPIX) return;
    int b = warp / LS, p = warp - b * LS;
    int hh = p / WW, ww = p - hh * WW;
    int tcol = ww * HH + hh;

    size_t base0 = (((size_t)(b * KD + 0)) * LS + p) * DD;
    size_t base1 = (((size_t)(b * KD + 1)) * LS + tcol) * DD;
    size_t base2 = (((size_t)(b * KD + 2)) * LS + (LS - 1 - p)) * DD;
    size_t base3 = (((size_t)(b * KD + 3)) * LS + (LS - 1 - tcol)) * DD;

    float v[6], s = 0.f, ss = 0.f;
#pragma unroll
    for (int j = 0; j < 6; j++) {
        int dd = lane + j * 32;
        float t = g_oy[base0 + dd] + g_oy[base1 + dd] + g_oy[base2 + dd] + g_oy[base3 + dd];
        v[j] = t; s += t; ss += t * t;
    }
#pragma unroll
    for (int o = 16; o > 0; o >>= 1) { s += __shfl_xor_sync(~0u, s, o); ss += __shfl_xor_sync(~0u, ss, o); }
    float m = s * (1.f / DD);
    float var = ss * (1.f / DD) - m * m;
    float inv = rsqrtf(var + 1e-5f);
#pragma unroll
    for (int j = 0; j < 6; j++) {
        int dd = lane + j * 32;
        float z = g_xz[((size_t)warp) * (2 * DD) + DD + dd];
        float yn = (v[j] - m) * inv * gno[dd] + bno[dd];
        g_ypost[(size_t)warp * DD + dd] = yn * siluf(z);
    }
}

// ---------------- residual 1 + LN_ffn ----------------
__global__ void resid1_lnffn(const float* __restrict__ x, const float* __restrict__ scale1,
                             const float* __restrict__ gf, const float* __restrict__ bf) {
    int warp = (blockIdx.x * blockDim.x + threadIdx.x) >> 5;
    int lane = threadIdx.x & 31;
    if (warp >= MPIX) return;
    int b = warp / LS, p = warp - b * LS;
    float v[3], s = 0.f, ss = 0.f;
#pragma unroll
    for (int j = 0; j < 3; j++) {
        int c = lane + j * 32;
        float t = g_t96[(size_t)warp * CC + c] + x[((size_t)(b * CC + c)) * LS + p] * scale1[c];
        v[j] = t; s += t; ss += t * t;
        g_x2[(size_t)warp * CC + c] = t;
    }
#pragma unroll
    for (int o = 16; o > 0; o >>= 1) { s += __shfl_xor_sync(~0u, s, o); ss += __shfl_xor_sync(~0u, ss, o); }
    float m = s * (1.f / CC);
    float var = ss * (1.f / CC) - m * m;
    float inv = rsqrtf(var + 1e-5f);
#pragma unroll
    for (int j = 0; j < 3; j++) {
        int c = lane + j * 32;
        g_h1n[(size_t)warp * CC + c] = (v[j] - m) * inv * gf[c] + bf[c];
    }
}

// ---------------- final: residual 2 + tiled transpose to (B,C,H,W) ----------------
__global__ void __launch_bounds__(256) final_kernel(const float* __restrict__ scale2,
                                                    float* __restrict__ out) {
    __shared__ float tile[CC][33];
    int b = blockIdx.y;
    int p0 = blockIdx.x * 32;
    int t = threadIdx.x;
    for (int idx = t; idx < 32 * CC; idx += 256) {
        int i = idx / CC;
        int c = idx - i * CC;
        size_t src = ((size_t)(b * LS + p0 + i)) * CC + c;
        tile[c][i] = g_t96[src] + g_x2[src] * scale2[c];
    }
    __syncthreads();
    for (int idx = t; idx < 32 * CC; idx += 256) {
        int c = idx >> 5;
        int i = idx & 31;
        out[((size_t)(b * CC + c)) * LS + p0 + i] = tile[c][i];
    }
}

// ---------------- launch ----------------
extern "C" void kernel_launch(void* const* d_in, const int* in_sizes, int n_in,
                              void* d_out, int out_size) {
    const float* x          = (const float*)d_in[0];
    const float* ln_in_g    = (const float*)d_in[1];
    const float* ln_in_b    = (const float*)d_in[2];
    const float* in_proj_w  = (const float*)d_in[3];
    const float* in_proj_b  = (const float*)d_in[4];
    const float* conv_w     = (const float*)d_in[5];
    const float* conv_b     = (const float*)d_in[6];
    const float* x_proj_w   = (const float*)d_in[7];
    const float* dt_w       = (const float*)d_in[8];
    const float* dt_b       = (const float*)d_in[9];
    const float* A_logs     = (const float*)d_in[10];
    const float* Ds         = (const float*)d_in[11];
    const float* out_norm_g = (const float*)d_in[12];
    const float* out_norm_b = (const float*)d_in[13];
    const float* out_proj_w = (const float*)d_in[14];
    const float* out_proj_b = (const float*)d_in[15];
    const float* ln_ffn_g   = (const float*)d_in[16];
    const float* ln_ffn_b   = (const float*)d_in[17];
    const float* fc1_w      = (const float*)d_in[18];
    const float* fc1_b      = (const float*)d_in[19];
    const float* fc2_w      = (const float*)d_in[20];
    const float* fc2_b      = (const float*)d_in[21];
    const float* scale1     = (const float*)d_in[22];
    const float* scale2     = (const float*)d_in[23];

    float *p_xn, *p_xz, *p_u, *p_xdbl, *p_ypost, *p_t96, *p_h1n, *p_t192;
    cudaGetSymbolAddress((void**)&p_xn,    g_xn);
    cudaGetSymbolAddress((void**)&p_xz,    g_xz);
    cudaGetSymbolAddress((void**)&p_u,     g_u);
    cudaGetSymbolAddress((void**)&p_xdbl,  g_xdbl);
    cudaGetSymbolAddress((void**)&p_ypost, g_ypost);
    cudaGetSymbolAddress((void**)&p_t96,   g_t96);
    cudaGetSymbolAddress((void**)&p_h1n,   g_h1n);
    cudaGetSymbolAddress((void**)&p_t192,  g_t192);

    // 1. LN over channels -> g_xn (B,L,C)
    ln_in_kernel<<<MPIX / 8, 256>>>(x, ln_in_g, ln_in_b);
    // 2. in_proj: (M,96)x(384,96)^T
    gemm2<0><<<dim3(384 / 64, MPIX / 128), 256>>>(p_xn, in_proj_w, in_proj_b, p_xz, MPIX, 2 * DD, CC);
    // 3. depthwise conv 3x3 + SiLU
    conv_silu_kernel<<<MPIX, DD>>>(conv_w, conv_b);
    // 4. x_proj: (M,192)x(152,192)^T
    gemm2<0><<<dim3(3, MPIX / 128), 256>>>(p_u, x_proj_w, nullptr, p_xdbl, MPIX, XD, DD);
    // 5-7. chunked selective scan
    scan_p1<<<BSZ * KD * NCH, DD>>>(dt_w, dt_b, A_logs);
    scan_p2<<<(BSZ * KD * DD * NS) / 256, 256>>>();
    scan_p3<<<BSZ * KD * NCH, DD>>>(dt_w, dt_b, A_logs, Ds);
    // 8. combine + LN + gate
    combine_ln_silu<<<MPIX / 8, 256>>>(out_norm_g, out_norm_b);
    // 9. out_proj: (M,192)x(96,192)^T
    gemm2<0><<<dim3(2, MPIX / 128), 256>>>(p_ypost, out_proj_w, out_proj_b, p_t96, MPIX, CC, DD);
    // 10. residual1 + LN_ffn
    resid1_lnffn<<<MPIX / 8, 256>>>(x, scale1, ln_ffn_g, ln_ffn_b);
    // 11. fc1 + leaky relu
    gemm2<1><<<dim3(3, MPIX / 128), 256>>>(p_h1n, fc1_w, fc1_b, p_t192, MPIX, DD, CC);
    // 12. fc2
    gemm2<0><<<dim3(2, MPIX / 128), 256>>>(p_t192, fc2_w, fc2_b, p_t96, MPIX, CC, DD);
    // 13. residual2 + transpose to (B,C,H,W)
    final_kernel<<<dim3(LS / 32, BSZ), 256>>>(scale2, (float*)d_out);
}